// round 15
// baseline (speedup 1.0000x reference)
#include <cuda_runtime.h>
#include <cuda_bf16.h>
#include <math.h>
#include <stdint.h>

#define B_  2
#define L_  2048
#define H_  1024
#define NH_ 16
#define HD_ 64
#define BH_ 32
#define M_  4096
#define MAXPOS_ 2048
#define NDIST 4095

// ---------------- device-global scratch (allocation-free) ----------------
__device__ __nv_bfloat16 g_hhi[(size_t)M_*H_];
__device__ __nv_bfloat16 g_hlo[(size_t)M_*H_];
__device__ __nv_bfloat16 g_whi[3][(size_t)H_*H_];
__device__ __nv_bfloat16 g_wlo[3][(size_t)H_*H_];
__device__ __nv_bfloat16 g_qhi[(size_t)BH_*L_*HD_];
__device__ __nv_bfloat16 g_qlo[(size_t)BH_*L_*HD_];
__device__ __nv_bfloat16 g_khi[(size_t)BH_*L_*HD_];
__device__ __nv_bfloat16 g_klo[(size_t)BH_*L_*HD_];
__device__ __nv_bfloat16 g_vhi[(size_t)BH_*L_*HD_];
__device__ __nv_bfloat16 g_vlo[(size_t)BH_*L_*HD_];
__device__ __nv_bfloat16 g_e[(size_t)NDIST*HD_];

// ---------------- helpers ----------------
__device__ __forceinline__ uint32_t smem_u32(const void* p){
    return (uint32_t)__cvta_generic_to_shared(p);
}
__device__ __forceinline__ void ldsm4(uint32_t* r, uint32_t a){
    asm volatile("ldmatrix.sync.aligned.m8n8.x4.shared.b16 {%0,%1,%2,%3}, [%4];"
        : "=r"(r[0]),"=r"(r[1]),"=r"(r[2]),"=r"(r[3]) : "r"(a));
}
__device__ __forceinline__ void ldsm4t(uint32_t* r, uint32_t a){
    asm volatile("ldmatrix.sync.aligned.m8n8.x4.trans.shared.b16 {%0,%1,%2,%3}, [%4];"
        : "=r"(r[0]),"=r"(r[1]),"=r"(r[2]),"=r"(r[3]) : "r"(a));
}
__device__ __forceinline__ void mma_bf16(float* c, const uint32_t* a, uint32_t b0, uint32_t b1){
    asm volatile(
        "mma.sync.aligned.m16n8k16.row.col.f32.bf16.bf16.f32 "
        "{%0,%1,%2,%3},{%4,%5,%6,%7},{%8,%9},{%0,%1,%2,%3};"
        : "+f"(c[0]), "+f"(c[1]), "+f"(c[2]), "+f"(c[3])
        : "r"(a[0]), "r"(a[1]), "r"(a[2]), "r"(a[3]), "r"(b0), "r"(b1));
}
__device__ __forceinline__ uint32_t packbf(float x, float y){
    __nv_bfloat162 h = __floats2bfloat162_rn(x, y);
    return *reinterpret_cast<uint32_t*>(&h);
}
__device__ __forceinline__ void cp16(uint32_t dst, const void* src){
    asm volatile("cp.async.cg.shared.global [%0], [%1], 16;" :: "r"(dst), "l"(src));
}
__device__ __forceinline__ void cp_commit_wait(){
    asm volatile("cp.async.commit_group;\n cp.async.wait_group 0;" ::: "memory");
}
// tiles have 128B rows (64 bf16); chunk = 16B unit, xor-swizzled
__device__ __forceinline__ uint32_t sw_addr(char* sm, int off, int row, int ch){
    return smem_u32(sm + off + row*128 + (((ch) ^ (row & 7)) << 4));
}

// ---------------- merged prep: fp32 -> bf16 hi/lo planes + e ----------------
#define N_H   (M_*H_)
#define N_W   (H_*H_)
#define N_E   (NDIST*HD_)
#define N_TOT (N_H + 3*N_W + N_E)

__global__ __launch_bounds__(256) void prep_all(
    const float* __restrict__ hidden, const float* __restrict__ Wq,
    const float* __restrict__ Wk, const float* __restrict__ Wv,
    const float* __restrict__ emb)
{
    int i = blockIdx.x*256 + threadIdx.x;
    if (i >= N_TOT) return;
    if (i >= N_H + 3*N_W){
        int j = i - (N_H + 3*N_W);
        g_e[j] = __float2bfloat16(emb[j]);
        return;
    }
    const float* src;  __nv_bfloat16 *hi, *lo;  int j;
    if (i < N_H){ src = hidden; hi = g_hhi; lo = g_hlo; j = i; }
    else if (i < N_H + N_W){ src = Wq; hi = g_whi[0]; lo = g_wlo[0]; j = i - N_H; }
    else if (i < N_H + 2*N_W){ src = Wk; hi = g_whi[1]; lo = g_wlo[1]; j = i - N_H - N_W; }
    else { src = Wv; hi = g_whi[2]; lo = g_wlo[2]; j = i - N_H - 2*N_W; }
    float x = src[j];
    __nv_bfloat16 h = __float2bfloat16(x);
    hi[j] = h;
    lo[j] = __float2bfloat16(x - __bfloat162float(h));
}

// ---------------- QKV projection via split-bf16 mma ----------------
#define QA_HI 0
#define QA_LO 16384
#define QB_HI 32768
#define QB_LO 40960
#define QKV_SMEM 49152

__global__ __launch_bounds__(128) void qkv_mma(
    const float* __restrict__ bq, const float* __restrict__ bk,
    const float* __restrict__ bv)
{
    extern __shared__ char sm[];
    const int which = blockIdx.z;
    const __nv_bfloat16* Whi = g_whi[which];
    const __nv_bfloat16* Wlo = g_wlo[which];
    const float* bias = (which==0) ? bq : (which==1) ? bk : bv;
    __nv_bfloat16* Ohi = (which==0) ? g_qhi : (which==1) ? g_khi : g_vhi;
    __nv_bfloat16* Olo = (which==0) ? g_qlo : (which==1) ? g_klo : g_vlo;

    const int m0 = blockIdx.y * 128;
    const int n0 = blockIdx.x * 64;
    const int t  = threadIdx.x;
    const int w  = t >> 5;
    const int lane = t & 31;
    const int quad = lane & 3;
    const int g8  = lane >> 3;
    const int il7 = lane & 7;

    float c[2][8][4];
#pragma unroll
    for (int s = 0; s < 2; s++)
#pragma unroll
        for (int n = 0; n < 8; n++)
#pragma unroll
            for (int j = 0; j < 4; j++) c[s][n][j] = 0.f;

    for (int k0 = 0; k0 < H_; k0 += 64){
        __syncthreads();
#pragma unroll
        for (int rep = 0; rep < 2; rep++){
            int id = t + 128*rep;
            int plane = id >> 7, row = id & 127;
            const char* gs = (const char*)((plane ? g_hlo : g_hhi) + (size_t)(m0+row)*H_ + k0);
            int off = (plane ? QA_LO : QA_HI);
#pragma unroll
            for (int cc = 0; cc < 8; cc++)
                cp16(sw_addr(sm, off, row, cc), gs + cc*16);
        }
        {
            int plane = t >> 6, row = t & 63;
            const char* gs = (const char*)((plane ? Wlo : Whi) + (size_t)(n0+row)*H_ + k0);
            int off = (plane ? QB_LO : QB_HI);
#pragma unroll
            for (int cc = 0; cc < 8; cc++)
                cp16(sw_addr(sm, off, row, cc), gs + cc*16);
        }
        cp_commit_wait();
        __syncthreads();

#pragma unroll
        for (int kk = 0; kk < 4; kk++){
            uint32_t ah[2][4], al[2][4];
#pragma unroll
            for (int s = 0; s < 2; s++){
                int row = 32*w + 16*s + (lane & 15);
                int ch  = 2*kk + (lane >> 4);
                ldsm4(ah[s], sw_addr(sm, QA_HI, row, ch));
                ldsm4(al[s], sw_addr(sm, QA_LO, row, ch));
            }
#pragma unroll
            for (int n2 = 0; n2 < 4; n2++){
                int row = 8*(2*n2 + (g8>>1)) + il7;
                int ch  = 2*kk + (g8&1);
                uint32_t bh4[4], bl4[4];
                ldsm4(bh4, sw_addr(sm, QB_HI, row, ch));
                ldsm4(bl4, sw_addr(sm, QB_LO, row, ch));
#pragma unroll
                for (int s = 0; s < 2; s++){
                    mma_bf16(c[s][2*n2  ], ah[s], bh4[0], bh4[1]);
                    mma_bf16(c[s][2*n2  ], ah[s], bl4[0], bl4[1]);
                    mma_bf16(c[s][2*n2  ], al[s], bh4[0], bh4[1]);
                    mma_bf16(c[s][2*n2+1], ah[s], bh4[2], bh4[3]);
                    mma_bf16(c[s][2*n2+1], ah[s], bl4[2], bl4[3]);
                    mma_bf16(c[s][2*n2+1], al[s], bh4[2], bh4[3]);
                }
            }
        }
    }

    const int h = n0 >> 6;
#pragma unroll
    for (int s = 0; s < 2; s++){
#pragma unroll
        for (int n = 0; n < 8; n++){
            int col = 8*n + 2*quad;
            float b0f = bias[n0+col], b1f = bias[n0+col+1];
#pragma unroll
            for (int half = 0; half < 2; half++){
                int mr = m0 + 32*w + 16*s + (lane>>2) + half*8;
                float f0 = c[s][n][half*2+0] + b0f;
                float f1 = c[s][n][half*2+1] + b1f;
                int b_ = mr >> 11, l = mr & (L_-1);
                size_t idx = (((size_t)(b_*NH_ + h))*L_ + l)*HD_ + col;
                __nv_bfloat16 h0 = __float2bfloat16(f0);
                __nv_bfloat16 h1 = __float2bfloat16(f1);
                __nv_bfloat162 hp = __halves2bfloat162(h0, h1);
                __nv_bfloat162 lp = __halves2bfloat162(
                    __float2bfloat16(f0 - __bfloat162float(h0)),
                    __float2bfloat16(f1 - __bfloat162float(h1)));
                *(uint32_t*)&Ohi[idx] = *(uint32_t*)&hp;
                *(uint32_t*)&Olo[idx] = *(uint32_t*)&lp;
            }
        }
    }
}

// ---------------- fused flash attention via mma ----------
#define OQ_HI 0
#define OQ_LO 8192
#define OK_HI 16384
#define OK_LO 24576
#define OV_HI 32768
#define OV_LO 40960
#define OE    49152
#define O_QE  65536
#define O_KE  82944
#define O_MSK 100352
#define FLASH_SMEM 108544

__global__ __launch_bounds__(128) void flash_kernel(
    const float* __restrict__ mask, float* __restrict__ out)
{
    extern __shared__ char sm[];
    const int bh = blockIdx.y;
    const int l0 = blockIdx.x * 64;
    const int t  = threadIdx.x;
    const int w  = t >> 5;
    const int lane = t & 31;
    const int quad = lane & 3;
    const int g8  = lane >> 3;
    const int il7 = lane & 7;
    const int lw = 16*w + (lane >> 2);
    const size_t gb = (size_t)bh * L_ * HD_;
    const int b_ = bh >> 4, head = bh & 15;

    // stage mask row (2048 floats) + Q hi/lo
    {
        const char* mp = (const char*)(mask + (size_t)b_ * L_);
#pragma unroll
        for (int i = 0; i < 4; i++)
            cp16(smem_u32(sm + O_MSK + (t + 128*i)*16), mp + (t + 128*i)*16);
        int plane = t >> 6, row = t & 63;
        const char* gs = (const char*)((plane ? g_qlo : g_qhi) + gb + (size_t)(l0+row)*HD_);
        int off = (plane ? OQ_LO : OQ_HI);
#pragma unroll
        for (int cc = 0; cc < 8; cc++)
            cp16(sw_addr(sm, off, row, cc), gs + cc*16);
    }
    cp_commit_wait();
    __syncthreads();

    // persistent Q A-fragments
    uint32_t qh[4][4], ql[4][4];
#pragma unroll
    for (int kk = 0; kk < 4; kk++){
        int row = 16*w + (lane & 15);
        int ch  = 2*kk + (lane >> 4);
        ldsm4(qh[kk], sw_addr(sm, OQ_HI, row, ch));
        ldsm4(ql[kk], sw_addr(sm, OQ_LO, row, ch));
    }

    float o[8][4];
#pragma unroll
    for (int n = 0; n < 8; n++)
#pragma unroll
        for (int j = 0; j < 4; j++) o[n][j] = 0.f;
    float ls0 = 0.f, ls1 = 0.f;    // running exp-sums (no max subtraction: logits are O(1))

    for (int r0 = 0; r0 < L_; r0 += 64){
        __syncthreads();
        // stage K,V hi/lo (4 tiles x 64 rows)
#pragma unroll
        for (int rep = 0; rep < 2; rep++){
            int id = t + 128*rep;
            int tile = id >> 6, row = id & 63;
            const char* g =
                (const char*)((tile==0 ? g_khi : tile==1 ? g_klo : tile==2 ? g_vhi : g_vlo)
                + gb + (size_t)(r0+row)*HD_);
            int off = (tile==0 ? OK_HI : tile==1 ? OK_LO : tile==2 ? OV_HI : OV_LO);
#pragma unroll
            for (int cc = 0; cc < 8; cc++)
                cp16(sw_addr(sm, off, row, cc), g + cc*16);
        }
        // stage E slab (rows 0..126; row 127 zeroed)
        {
            int gbase = l0 - r0 + (MAXPOS_ - 1) - 63;
            if (t < 127){
                const char* gs = (const char*)(g_e + (size_t)(gbase + t)*HD_);
#pragma unroll
                for (int cc = 0; cc < 8; cc++)
                    cp16(sw_addr(sm, OE, t, cc), gs + cc*16);
            } else if (t == 127){
                uint4 z = make_uint4(0,0,0,0);
                char* d = sm + OE + 127*128;
#pragma unroll
                for (int cc = 0; cc < 8; cc++)
                    *(uint4*)(d + ((cc ^ 7) << 4)) = z;
            }
        }
        cp_commit_wait();
        __syncthreads();

        // ---- QE/KE bias GEMMs, band-trimmed ----
        {
            uint32_t ka[4][4];
#pragma unroll
            for (int kk = 0; kk < 4; kk++){
                int row = 16*w + (lane & 15);
                int ch  = 2*kk + (lane >> 4);
                ldsm4(ka[kk], sw_addr(sm, OK_HI, row, ch));
            }
            __nv_bfloat16* qe = (__nv_bfloat16*)(sm + O_QE);
            __nv_bfloat16* ke = (__nv_bfloat16*)(sm + O_KE);
            const int nq0 = 2*w;
            const int nk0 = 6 - 2*w;
#pragma unroll
            for (int p = 0; p < 5; p++){
                float cq[2][4] = {{0.f,0.f,0.f,0.f},{0.f,0.f,0.f,0.f}};
                float ck[2][4] = {{0.f,0.f,0.f,0.f},{0.f,0.f,0.f,0.f}};
#pragma unroll
                for (int kk = 0; kk < 4; kk++){
                    int ch = 2*kk + (g8&1);
                    uint32_t eq[4], ek[4];
                    ldsm4(eq, sw_addr(sm, OE, 8*(nq0 + 2*p + (g8>>1)) + il7, ch));
                    ldsm4(ek, sw_addr(sm, OE, 8*(nk0 + 2*p + (g8>>1)) + il7, ch));
                    mma_bf16(cq[0], qh[kk], eq[0], eq[1]);
                    mma_bf16(cq[1], qh[kk], eq[2], eq[3]);
                    mma_bf16(ck[0], ka[kk], ek[0], ek[1]);
                    mma_bf16(ck[1], ka[kk], ek[2], ek[3]);
                }
#pragma unroll
                for (int u = 0; u < 2; u++){
                    int cq_col = 8*(nq0 + 2*p + u) + 2*quad;
                    int ck_col = 8*(nk0 + 2*p + u) + 2*quad;
                    *(uint32_t*)&qe[(size_t)lw*136 + cq_col]     = packbf(cq[u][0], cq[u][1]);
                    *(uint32_t*)&qe[(size_t)(lw+8)*136 + cq_col] = packbf(cq[u][2], cq[u][3]);
                    *(uint32_t*)&ke[(size_t)lw*136 + ck_col]     = packbf(ck[u][0], ck[u][1]);
                    *(uint32_t*)&ke[(size_t)(lw+8)*136 + ck_col] = packbf(ck[u][2], ck[u][3]);
                }
            }
        }
        __syncthreads();

        // ---- S1 = Q@K^T (3-mma split), kk OUTER for accumulator ILP ----
        float sc[8][4];
        const __nv_bfloat16* qe = (const __nv_bfloat16*)(sm + O_QE);
        const __nv_bfloat16* ke = (const __nv_bfloat16*)(sm + O_KE);
#pragma unroll
        for (int n = 0; n < 8; n++){
            int r  = 8*n + 2*quad;
            int d0 = lw - r + 63;
            sc[n][0] = __bfloat162float(qe[(size_t)lw*136 + d0])
                     + __bfloat162float(ke[(size_t)r*136 + d0]);
            sc[n][1] = __bfloat162float(qe[(size_t)lw*136 + d0 - 1])
                     + __bfloat162float(ke[(size_t)(r+1)*136 + d0 - 1]);
            sc[n][2] = __bfloat162float(qe[(size_t)(lw+8)*136 + d0 + 8])
                     + __bfloat162float(ke[(size_t)r*136 + d0 + 8]);
            sc[n][3] = __bfloat162float(qe[(size_t)(lw+8)*136 + d0 + 7])
                     + __bfloat162float(ke[(size_t)(r+1)*136 + d0 + 7]);
        }
#pragma unroll
        for (int kk = 0; kk < 4; kk++){
#pragma unroll
            for (int n2 = 0; n2 < 4; n2++){
                int row = 8*(2*n2 + (g8>>1)) + il7;
                int ch  = 2*kk + (g8&1);
                uint32_t kh4[4], kl4[4];
                ldsm4(kh4, sw_addr(sm, OK_HI, row, ch));
                ldsm4(kl4, sw_addr(sm, OK_LO, row, ch));
                mma_bf16(sc[2*n2  ], qh[kk], kh4[0], kh4[1]);
                mma_bf16(sc[2*n2  ], qh[kk], kl4[0], kl4[1]);
                mma_bf16(sc[2*n2  ], ql[kk], kh4[0], kh4[1]);
                mma_bf16(sc[2*n2+1], qh[kk], kh4[2], kh4[3]);
                mma_bf16(sc[2*n2+1], qh[kk], kl4[2], kl4[3]);
                mma_bf16(sc[2*n2+1], ql[kk], kh4[2], kh4[3]);
            }
        }

        // logits = sc*0.125 + mask
        const float* msf = (const float*)(sm + O_MSK);
#pragma unroll
        for (int n = 0; n < 8; n++){
            float2 mk = *(const float2*)&msf[r0 + 8*n + 2*quad];
            sc[n][0] = sc[n][0]*0.125f + mk.x;
            sc[n][1] = sc[n][1]*0.125f + mk.y;
            sc[n][2] = sc[n][2]*0.125f + mk.x;
            sc[n][3] = sc[n][3]*0.125f + mk.y;
        }

        // ---- softmax without running max (logits O(1); exp overflow-free) ----
        float s0 = 0.f, s1 = 0.f;
        uint32_t ph[8][2], pl[8][2];
#pragma unroll
        for (int n = 0; n < 8; n++){
            float e0 = __expf(sc[n][0]);
            float e1 = __expf(sc[n][1]);
            float e2 = __expf(sc[n][2]);
            float e3 = __expf(sc[n][3]);
            s0 += e0 + e1;  s1 += e2 + e3;
            __nv_bfloat16 h0 = __float2bfloat16(e0), h1 = __float2bfloat16(e1);
            __nv_bfloat16 h2 = __float2bfloat16(e2), h3 = __float2bfloat16(e3);
            __nv_bfloat162 p0 = __halves2bfloat162(h0, h1);
            __nv_bfloat162 p1 = __halves2bfloat162(h2, h3);
            ph[n][0] = *(uint32_t*)&p0;
            ph[n][1] = *(uint32_t*)&p1;
            pl[n][0] = packbf(e0 - __bfloat162float(h0), e1 - __bfloat162float(h1));
            pl[n][1] = packbf(e2 - __bfloat162float(h2), e3 - __bfloat162float(h3));
        }
        s0 += __shfl_xor_sync(0xffffffffu, s0, 1);
        s0 += __shfl_xor_sync(0xffffffffu, s0, 2);
        s1 += __shfl_xor_sync(0xffffffffu, s1, 1);
        s1 += __shfl_xor_sync(0xffffffffu, s1, 2);
        ls0 += s0;
        ls1 += s1;

        // ---- PV: O += P @ V (no rescale; straight accumulation) ----
        const int il16 = lane & 15;
        const int gt   = lane >> 4;
#pragma unroll
        for (int kk = 0; kk < 4; kk++){
            uint32_t ah[4] = { ph[2*kk][0], ph[2*kk][1], ph[2*kk+1][0], ph[2*kk+1][1] };
            uint32_t al_[4]= { pl[2*kk][0], pl[2*kk][1], pl[2*kk+1][0], pl[2*kk+1][1] };
#pragma unroll
            for (int n2 = 0; n2 < 4; n2++){
                int row = 16*kk + il16;
                int ch  = 2*n2 + gt;
                uint32_t vh4[4], vl4[4];
                ldsm4t(vh4, sw_addr(sm, OV_HI, row, ch));
                ldsm4t(vl4, sw_addr(sm, OV_LO, row, ch));
                mma_bf16(o[2*n2  ], ah,  vh4[0], vh4[1]);
                mma_bf16(o[2*n2  ], ah,  vl4[0], vl4[1]);
                mma_bf16(o[2*n2  ], al_, vh4[0], vh4[1]);
                mma_bf16(o[2*n2+1], ah,  vh4[2], vh4[3]);
                mma_bf16(o[2*n2+1], ah,  vl4[2], vl4[3]);
                mma_bf16(o[2*n2+1], al_, vh4[2], vh4[3]);
            }
        }
    }

    // epilogue
    const float inv0 = 1.0f / ls0;
    const float inv1 = 1.0f / ls1;
#pragma unroll
    for (int n = 0; n < 8; n++){
        int col = head*64 + 8*n + 2*quad;
        float2 r0v = make_float2(o[n][0]*inv0, o[n][1]*inv0);
        float2 r1v = make_float2(o[n][2]*inv1, o[n][3]*inv1);
        *(float2*)&out[((size_t)b_*L_ + l0 + lw    )*H_ + col] = r0v;
        *(float2*)&out[((size_t)b_*L_ + l0 + lw + 8)*H_ + col] = r1v;
    }
}

// ---------------------------------------------------------------------------
extern "C" void kernel_launch(void* const* d_in, const int* in_sizes, int n_in,
                              void* d_out, int out_size)
{
    const float* hidden   = (const float*)d_in[0];
    const float* mask     = (const float*)d_in[1];
    const float* Wq       = (const float*)d_in[2];
    const float* bq       = (const float*)d_in[3];
    const float* Wk       = (const float*)d_in[4];
    const float* bk       = (const float*)d_in[5];
    const float* Wv       = (const float*)d_in[6];
    const float* bv       = (const float*)d_in[7];
    const float* dist_emb = (const float*)d_in[8];
    float* out            = (float*)d_out;

    cudaFuncSetAttribute(qkv_mma,
        cudaFuncAttributeMaxDynamicSharedMemorySize, QKV_SMEM);
    cudaFuncSetAttribute(flash_kernel,
        cudaFuncAttributeMaxDynamicSharedMemorySize, FLASH_SMEM);

    prep_all<<<(N_TOT + 255)/256, 256>>>(hidden, Wq, Wk, Wv, dist_emb);
    qkv_mma<<<dim3(H_/64, M_/128, 3), 128, QKV_SMEM>>>(bq, bk, bv);
    flash_kernel<<<dim3(L_/64, BH_), 128, FLASH_SMEM>>>(mask, out);
}

// round 17
// speedup vs baseline: 1.0645x; 1.0645x over previous
#include <cuda_runtime.h>
#include <cuda_bf16.h>
#include <math.h>
#include <stdint.h>

#define B_  2
#define L_  2048
#define H_  1024
#define NH_ 16
#define HD_ 64
#define BH_ 32
#define M_  4096
#define MAXPOS_ 2048
#define NDIST 4095

// ---------------- device-global scratch (allocation-free) ----------------
__device__ __nv_bfloat16 g_hhi[(size_t)M_*H_];
__device__ __nv_bfloat16 g_hlo[(size_t)M_*H_];
__device__ __nv_bfloat16 g_whi[3][(size_t)H_*H_];
__device__ __nv_bfloat16 g_wlo[3][(size_t)H_*H_];
__device__ __nv_bfloat16 g_qhi[(size_t)BH_*L_*HD_];
__device__ __nv_bfloat16 g_qlo[(size_t)BH_*L_*HD_];
__device__ __nv_bfloat16 g_khi[(size_t)BH_*L_*HD_];
__device__ __nv_bfloat16 g_klo[(size_t)BH_*L_*HD_];
__device__ __nv_bfloat16 g_vhi[(size_t)BH_*L_*HD_];
__device__ __nv_bfloat16 g_vlo[(size_t)BH_*L_*HD_];
__device__ __nv_bfloat16 g_e[(size_t)NDIST*HD_];

// ---------------- helpers ----------------
__device__ __forceinline__ uint32_t smem_u32(const void* p){
    return (uint32_t)__cvta_generic_to_shared(p);
}
__device__ __forceinline__ void ldsm4(uint32_t* r, uint32_t a){
    asm volatile("ldmatrix.sync.aligned.m8n8.x4.shared.b16 {%0,%1,%2,%3}, [%4];"
        : "=r"(r[0]),"=r"(r[1]),"=r"(r[2]),"=r"(r[3]) : "r"(a));
}
__device__ __forceinline__ void ldsm4t(uint32_t* r, uint32_t a){
    asm volatile("ldmatrix.sync.aligned.m8n8.x4.trans.shared.b16 {%0,%1,%2,%3}, [%4];"
        : "=r"(r[0]),"=r"(r[1]),"=r"(r[2]),"=r"(r[3]) : "r"(a));
}
__device__ __forceinline__ void mma_bf16(float* c, const uint32_t* a, uint32_t b0, uint32_t b1){
    asm volatile(
        "mma.sync.aligned.m16n8k16.row.col.f32.bf16.bf16.f32 "
        "{%0,%1,%2,%3},{%4,%5,%6,%7},{%8,%9},{%0,%1,%2,%3};"
        : "+f"(c[0]), "+f"(c[1]), "+f"(c[2]), "+f"(c[3])
        : "r"(a[0]), "r"(a[1]), "r"(a[2]), "r"(a[3]), "r"(b0), "r"(b1));
}
__device__ __forceinline__ uint32_t packbf(float x, float y){
    __nv_bfloat162 h = __floats2bfloat162_rn(x, y);
    return *reinterpret_cast<uint32_t*>(&h);
}
__device__ __forceinline__ void cp16(uint32_t dst, const void* src){
    asm volatile("cp.async.cg.shared.global [%0], [%1], 16;" :: "r"(dst), "l"(src));
}
__device__ __forceinline__ void cp_commit_wait(){
    asm volatile("cp.async.commit_group;\n cp.async.wait_group 0;" ::: "memory");
}
// tiles have 128B rows (64 bf16); chunk = 16B unit, xor-swizzled
__device__ __forceinline__ uint32_t sw_addr(char* sm, int off, int row, int ch){
    return smem_u32(sm + off + row*128 + (((ch) ^ (row & 7)) << 4));
}

// ---------------- merged prep: fp32 -> bf16 hi/lo planes + e ----------------
#define N_H   (M_*H_)
#define N_W   (H_*H_)
#define N_E   (NDIST*HD_)
#define N_TOT (N_H + 3*N_W + N_E)

__global__ __launch_bounds__(256) void prep_all(
    const float* __restrict__ hidden, const float* __restrict__ Wq,
    const float* __restrict__ Wk, const float* __restrict__ Wv,
    const float* __restrict__ emb)
{
    int i = blockIdx.x*256 + threadIdx.x;
    if (i >= N_TOT) return;
    if (i >= N_H + 3*N_W){
        int j = i - (N_H + 3*N_W);
        g_e[j] = __float2bfloat16(emb[j]);
        return;
    }
    const float* src;  __nv_bfloat16 *hi, *lo;  int j;
    if (i < N_H){ src = hidden; hi = g_hhi; lo = g_hlo; j = i; }
    else if (i < N_H + N_W){ src = Wq; hi = g_whi[0]; lo = g_wlo[0]; j = i - N_H; }
    else if (i < N_H + 2*N_W){ src = Wk; hi = g_whi[1]; lo = g_wlo[1]; j = i - N_H - N_W; }
    else { src = Wv; hi = g_whi[2]; lo = g_wlo[2]; j = i - N_H - 2*N_W; }
    float x = src[j];
    __nv_bfloat16 h = __float2bfloat16(x);
    hi[j] = h;
    lo[j] = __float2bfloat16(x - __bfloat162float(h));
}

// ---------------- QKV projection via split-bf16 mma ----------------
#define QA_HI 0
#define QA_LO 16384
#define QB_HI 32768
#define QB_LO 40960
#define QKV_SMEM 49152

__global__ __launch_bounds__(128) void qkv_mma(
    const float* __restrict__ bq, const float* __restrict__ bk,
    const float* __restrict__ bv)
{
    extern __shared__ char sm[];
    const int which = blockIdx.z;
    const __nv_bfloat16* Whi = g_whi[which];
    const __nv_bfloat16* Wlo = g_wlo[which];
    const float* bias = (which==0) ? bq : (which==1) ? bk : bv;
    __nv_bfloat16* Ohi = (which==0) ? g_qhi : (which==1) ? g_khi : g_vhi;
    __nv_bfloat16* Olo = (which==0) ? g_qlo : (which==1) ? g_klo : g_vlo;

    const int m0 = blockIdx.y * 128;
    const int n0 = blockIdx.x * 64;
    const int t  = threadIdx.x;
    const int w  = t >> 5;
    const int lane = t & 31;
    const int quad = lane & 3;
    const int g8  = lane >> 3;
    const int il7 = lane & 7;

    float c[2][8][4];
#pragma unroll
    for (int s = 0; s < 2; s++)
#pragma unroll
        for (int n = 0; n < 8; n++)
#pragma unroll
            for (int j = 0; j < 4; j++) c[s][n][j] = 0.f;

    for (int k0 = 0; k0 < H_; k0 += 64){
        __syncthreads();
#pragma unroll
        for (int rep = 0; rep < 2; rep++){
            int id = t + 128*rep;
            int plane = id >> 7, row = id & 127;
            const char* gs = (const char*)((plane ? g_hlo : g_hhi) + (size_t)(m0+row)*H_ + k0);
            int off = (plane ? QA_LO : QA_HI);
#pragma unroll
            for (int cc = 0; cc < 8; cc++)
                cp16(sw_addr(sm, off, row, cc), gs + cc*16);
        }
        {
            int plane = t >> 6, row = t & 63;
            const char* gs = (const char*)((plane ? Wlo : Whi) + (size_t)(n0+row)*H_ + k0);
            int off = (plane ? QB_LO : QB_HI);
#pragma unroll
            for (int cc = 0; cc < 8; cc++)
                cp16(sw_addr(sm, off, row, cc), gs + cc*16);
        }
        cp_commit_wait();
        __syncthreads();

#pragma unroll
        for (int kk = 0; kk < 4; kk++){
            uint32_t ah[2][4], al[2][4];
#pragma unroll
            for (int s = 0; s < 2; s++){
                int row = 32*w + 16*s + (lane & 15);
                int ch  = 2*kk + (lane >> 4);
                ldsm4(ah[s], sw_addr(sm, QA_HI, row, ch));
                ldsm4(al[s], sw_addr(sm, QA_LO, row, ch));
            }
#pragma unroll
            for (int n2 = 0; n2 < 4; n2++){
                int row = 8*(2*n2 + (g8>>1)) + il7;
                int ch  = 2*kk + (g8&1);
                uint32_t bh4[4], bl4[4];
                ldsm4(bh4, sw_addr(sm, QB_HI, row, ch));
                ldsm4(bl4, sw_addr(sm, QB_LO, row, ch));
#pragma unroll
                for (int s = 0; s < 2; s++){
                    mma_bf16(c[s][2*n2  ], ah[s], bh4[0], bh4[1]);
                    mma_bf16(c[s][2*n2  ], ah[s], bl4[0], bl4[1]);
                    mma_bf16(c[s][2*n2  ], al[s], bh4[0], bh4[1]);
                    mma_bf16(c[s][2*n2+1], ah[s], bh4[2], bh4[3]);
                    mma_bf16(c[s][2*n2+1], ah[s], bl4[2], bl4[3]);
                    mma_bf16(c[s][2*n2+1], al[s], bh4[2], bh4[3]);
                }
            }
        }
    }

    const int h = n0 >> 6;
#pragma unroll
    for (int s = 0; s < 2; s++){
#pragma unroll
        for (int n = 0; n < 8; n++){
            int col = 8*n + 2*quad;
            float b0f = bias[n0+col], b1f = bias[n0+col+1];
#pragma unroll
            for (int half = 0; half < 2; half++){
                int mr = m0 + 32*w + 16*s + (lane>>2) + half*8;
                float f0 = c[s][n][half*2+0] + b0f;
                float f1 = c[s][n][half*2+1] + b1f;
                int b_ = mr >> 11, l = mr & (L_-1);
                size_t idx = (((size_t)(b_*NH_ + h))*L_ + l)*HD_ + col;
                __nv_bfloat16 h0 = __float2bfloat16(f0);
                __nv_bfloat16 h1 = __float2bfloat16(f1);
                __nv_bfloat162 hp = __halves2bfloat162(h0, h1);
                __nv_bfloat162 lp = __halves2bfloat162(
                    __float2bfloat16(f0 - __bfloat162float(h0)),
                    __float2bfloat16(f1 - __bfloat162float(h1)));
                *(uint32_t*)&Ohi[idx] = *(uint32_t*)&hp;
                *(uint32_t*)&Olo[idx] = *(uint32_t*)&lp;
            }
        }
    }
}

// ---------------- fused flash attention via mma (R12 structure) ----------
#define OQ_HI 0
#define OQ_LO 8192
#define OK_HI 16384
#define OK_LO 24576
#define OV_HI 32768
#define OV_LO 40960
#define OE    49152
#define O_QE  65536
#define O_KE  82944
#define O_MSK 100352
#define FLASH_SMEM 108544

__global__ __launch_bounds__(128) void flash_kernel(
    const float* __restrict__ mask, float* __restrict__ out)
{
    extern __shared__ char sm[];
    const int bh = blockIdx.y;
    const int l0 = blockIdx.x * 64;
    const int t  = threadIdx.x;
    const int w  = t >> 5;
    const int lane = t & 31;
    const int quad = lane & 3;
    const int g8  = lane >> 3;
    const int il7 = lane & 7;
    const int lw = 16*w + (lane >> 2);
    const size_t gb = (size_t)bh * L_ * HD_;
    const int b_ = bh >> 4, head = bh & 15;

    // stage mask row (2048 floats) + Q hi/lo
    {
        const char* mp = (const char*)(mask + (size_t)b_ * L_);
#pragma unroll
        for (int i = 0; i < 4; i++)
            cp16(smem_u32(sm + O_MSK + (t + 128*i)*16), mp + (t + 128*i)*16);
        int plane = t >> 6, row = t & 63;
        const char* gs = (const char*)((plane ? g_qlo : g_qhi) + gb + (size_t)(l0+row)*HD_);
        int off = (plane ? OQ_LO : OQ_HI);
#pragma unroll
        for (int cc = 0; cc < 8; cc++)
            cp16(sw_addr(sm, off, row, cc), gs + cc*16);
    }
    cp_commit_wait();
    __syncthreads();

    // persistent Q A-fragments
    uint32_t qh[4][4], ql[4][4];
#pragma unroll
    for (int kk = 0; kk < 4; kk++){
        int row = 16*w + (lane & 15);
        int ch  = 2*kk + (lane >> 4);
        ldsm4(qh[kk], sw_addr(sm, OQ_HI, row, ch));
        ldsm4(ql[kk], sw_addr(sm, OQ_LO, row, ch));
    }

    float o[8][4];
#pragma unroll
    for (int n = 0; n < 8; n++)
#pragma unroll
        for (int j = 0; j < 4; j++) o[n][j] = 0.f;
    float ls0 = 0.f, ls1 = 0.f;   // plain exp-sums; no running max (logits O(1))

    for (int r0 = 0; r0 < L_; r0 += 64){
        __syncthreads();
        // stage K,V hi/lo (4 tiles x 64 rows)
#pragma unroll
        for (int rep = 0; rep < 2; rep++){
            int id = t + 128*rep;
            int tile = id >> 6, row = id & 63;
            const char* g =
                (const char*)((tile==0 ? g_khi : tile==1 ? g_klo : tile==2 ? g_vhi : g_vlo)
                + gb + (size_t)(r0+row)*HD_);
            int off = (tile==0 ? OK_HI : tile==1 ? OK_LO : tile==2 ? OV_HI : OV_LO);
#pragma unroll
            for (int cc = 0; cc < 8; cc++)
                cp16(sw_addr(sm, off, row, cc), g + cc*16);
        }
        // stage E slab (rows 0..126; row 127 zeroed)
        {
            int gbase = l0 - r0 + (MAXPOS_ - 1) - 63;
            if (t < 127){
                const char* gs = (const char*)(g_e + (size_t)(gbase + t)*HD_);
#pragma unroll
                for (int cc = 0; cc < 8; cc++)
                    cp16(sw_addr(sm, OE, t, cc), gs + cc*16);
            } else if (t == 127){
                uint4 z = make_uint4(0,0,0,0);
                char* d = sm + OE + 127*128;
#pragma unroll
                for (int cc = 0; cc < 8; cc++)
                    *(uint4*)(d + ((cc ^ 7) << 4)) = z;
            }
        }
        cp_commit_wait();
        __syncthreads();

        // ---- QE/KE bias GEMMs, band-trimmed ----
        {
            uint32_t ka[4][4];
#pragma unroll
            for (int kk = 0; kk < 4; kk++){
                int row = 16*w + (lane & 15);
                int ch  = 2*kk + (lane >> 4);
                ldsm4(ka[kk], sw_addr(sm, OK_HI, row, ch));
            }
            __nv_bfloat16* qe = (__nv_bfloat16*)(sm + O_QE);
            __nv_bfloat16* ke = (__nv_bfloat16*)(sm + O_KE);
            const int nq0 = 2*w;
            const int nk0 = 6 - 2*w;
#pragma unroll
            for (int p = 0; p < 5; p++){
                float cq[2][4] = {{0.f,0.f,0.f,0.f},{0.f,0.f,0.f,0.f}};
                float ck[2][4] = {{0.f,0.f,0.f,0.f},{0.f,0.f,0.f,0.f}};
#pragma unroll
                for (int kk = 0; kk < 4; kk++){
                    int ch = 2*kk + (g8&1);
                    uint32_t eq[4], ek[4];
                    ldsm4(eq, sw_addr(sm, OE, 8*(nq0 + 2*p + (g8>>1)) + il7, ch));
                    ldsm4(ek, sw_addr(sm, OE, 8*(nk0 + 2*p + (g8>>1)) + il7, ch));
                    mma_bf16(cq[0], qh[kk], eq[0], eq[1]);
                    mma_bf16(cq[1], qh[kk], eq[2], eq[3]);
                    mma_bf16(ck[0], ka[kk], ek[0], ek[1]);
                    mma_bf16(ck[1], ka[kk], ek[2], ek[3]);
                }
#pragma unroll
                for (int u = 0; u < 2; u++){
                    int cq_col = 8*(nq0 + 2*p + u) + 2*quad;
                    int ck_col = 8*(nk0 + 2*p + u) + 2*quad;
                    *(uint32_t*)&qe[(size_t)lw*136 + cq_col]     = packbf(cq[u][0], cq[u][1]);
                    *(uint32_t*)&qe[(size_t)(lw+8)*136 + cq_col] = packbf(cq[u][2], cq[u][3]);
                    *(uint32_t*)&ke[(size_t)lw*136 + ck_col]     = packbf(ck[u][0], ck[u][1]);
                    *(uint32_t*)&ke[(size_t)(lw+8)*136 + ck_col] = packbf(ck[u][2], ck[u][3]);
                }
            }
        }
        __syncthreads();

        // ---- S1 = Q@K^T (3-mma split), R12 loop order (n2 outer) ----
        float sc[8][4];
        const __nv_bfloat16* qe = (const __nv_bfloat16*)(sm + O_QE);
        const __nv_bfloat16* ke = (const __nv_bfloat16*)(sm + O_KE);
#pragma unroll
        for (int n = 0; n < 8; n++){
            int r  = 8*n + 2*quad;
            int d0 = lw - r + 63;
            sc[n][0] = __bfloat162float(qe[(size_t)lw*136 + d0])
                     + __bfloat162float(ke[(size_t)r*136 + d0]);
            sc[n][1] = __bfloat162float(qe[(size_t)lw*136 + d0 - 1])
                     + __bfloat162float(ke[(size_t)(r+1)*136 + d0 - 1]);
            sc[n][2] = __bfloat162float(qe[(size_t)(lw+8)*136 + d0 + 8])
                     + __bfloat162float(ke[(size_t)r*136 + d0 + 8]);
            sc[n][3] = __bfloat162float(qe[(size_t)(lw+8)*136 + d0 + 7])
                     + __bfloat162float(ke[(size_t)(r+1)*136 + d0 + 7]);
        }
#pragma unroll
        for (int n2 = 0; n2 < 4; n2++){
#pragma unroll
            for (int kk = 0; kk < 4; kk++){
                int row = 8*(2*n2 + (g8>>1)) + il7;
                int ch  = 2*kk + (g8&1);
                uint32_t kh4[4], kl4[4];
                ldsm4(kh4, sw_addr(sm, OK_HI, row, ch));
                ldsm4(kl4, sw_addr(sm, OK_LO, row, ch));
                mma_bf16(sc[2*n2  ], qh[kk], kh4[0], kh4[1]);
                mma_bf16(sc[2*n2  ], qh[kk], kl4[0], kl4[1]);
                mma_bf16(sc[2*n2  ], ql[kk], kh4[0], kh4[1]);
                mma_bf16(sc[2*n2+1], qh[kk], kh4[2], kh4[3]);
                mma_bf16(sc[2*n2+1], qh[kk], kl4[2], kl4[3]);
                mma_bf16(sc[2*n2+1], ql[kk], kh4[2], kh4[3]);
            }
        }

        // logits = sc*0.125 + mask
        const float* msf = (const float*)(sm + O_MSK);
#pragma unroll
        for (int n = 0; n < 8; n++){
            float2 mk = *(const float2*)&msf[r0 + 8*n + 2*quad];
            sc[n][0] = sc[n][0]*0.125f + mk.x;
            sc[n][1] = sc[n][1]*0.125f + mk.y;
            sc[n][2] = sc[n][2]*0.125f + mk.x;
            sc[n][3] = sc[n][3]*0.125f + mk.y;
        }

        // ---- softmax without running max (logits O(1); exp overflow-free) ----
        float s0 = 0.f, s1 = 0.f;
        uint32_t ph[8][2], pl[8][2];
#pragma unroll
        for (int n = 0; n < 8; n++){
            float e0 = __expf(sc[n][0]);
            float e1 = __expf(sc[n][1]);
            float e2 = __expf(sc[n][2]);
            float e3 = __expf(sc[n][3]);
            s0 += e0 + e1;  s1 += e2 + e3;
            __nv_bfloat16 h0 = __float2bfloat16(e0), h1 = __float2bfloat16(e1);
            __nv_bfloat16 h2 = __float2bfloat16(e2), h3 = __float2bfloat16(e3);
            __nv_bfloat162 p0 = __halves2bfloat162(h0, h1);
            __nv_bfloat162 p1 = __halves2bfloat162(h2, h3);
            ph[n][0] = *(uint32_t*)&p0;
            ph[n][1] = *(uint32_t*)&p1;
            pl[n][0] = packbf(e0 - __bfloat162float(h0), e1 - __bfloat162float(h1));
            pl[n][1] = packbf(e2 - __bfloat162float(h2), e3 - __bfloat162float(h3));
        }
        s0 += __shfl_xor_sync(0xffffffffu, s0, 1);
        s0 += __shfl_xor_sync(0xffffffffu, s0, 2);
        s1 += __shfl_xor_sync(0xffffffffu, s1, 1);
        s1 += __shfl_xor_sync(0xffffffffu, s1, 2);
        ls0 += s0;
        ls1 += s1;

        // ---- PV: O += P @ V (no rescale; straight accumulation) ----
        const int il16 = lane & 15;
        const int gt   = lane >> 4;
#pragma unroll
        for (int kk = 0; kk < 4; kk++){
            uint32_t ah[4] = { ph[2*kk][0], ph[2*kk][1], ph[2*kk+1][0], ph[2*kk+1][1] };
            uint32_t al_[4]= { pl[2*kk][0], pl[2*kk][1], pl[2*kk+1][0], pl[2*kk+1][1] };
#pragma unroll
            for (int n2 = 0; n2 < 4; n2++){
                int row = 16*kk + il16;
                int ch  = 2*n2 + gt;
                uint32_t vh4[4], vl4[4];
                ldsm4t(vh4, sw_addr(sm, OV_HI, row, ch));
                ldsm4t(vl4, sw_addr(sm, OV_LO, row, ch));
                mma_bf16(o[2*n2  ], ah,  vh4[0], vh4[1]);
                mma_bf16(o[2*n2  ], ah,  vl4[0], vl4[1]);
                mma_bf16(o[2*n2  ], al_, vh4[0], vh4[1]);
                mma_bf16(o[2*n2+1], ah,  vh4[2], vh4[3]);
                mma_bf16(o[2*n2+1], ah,  vl4[2], vl4[3]);
                mma_bf16(o[2*n2+1], al_, vh4[2], vh4[3]);
            }
        }
    }

    // epilogue
    const float inv0 = 1.0f / ls0;
    const float inv1 = 1.0f / ls1;
#pragma unroll
    for (int n = 0; n < 8; n++){
        int col = head*64 + 8*n + 2*quad;
        float2 r0v = make_float2(o[n][0]*inv0, o[n][1]*inv0);
        float2 r1v = make_float2(o[n][2]*inv1, o[n][3]*inv1);
        *(float2*)&out[((size_t)b_*L_ + l0 + lw    )*H_ + col] = r0v;
        *(float2*)&out[((size_t)b_*L_ + l0 + lw + 8)*H_ + col] = r1v;
    }
}

// ---------------------------------------------------------------------------
extern "C" void kernel_launch(void* const* d_in, const int* in_sizes, int n_in,
                              void* d_out, int out_size)
{
    const float* hidden   = (const float*)d_in[0];
    const float* mask     = (const float*)d_in[1];
    const float* Wq       = (const float*)d_in[2];
    const float* bq       = (const float*)d_in[3];
    const float* Wk       = (const float*)d_in[4];
    const float* bk       = (const float*)d_in[5];
    const float* Wv       = (const float*)d_in[6];
    const float* bv       = (const float*)d_in[7];
    const float* dist_emb = (const float*)d_in[8];
    float* out            = (float*)d_out;

    cudaFuncSetAttribute(qkv_mma,
        cudaFuncAttributeMaxDynamicSharedMemorySize, QKV_SMEM);
    cudaFuncSetAttribute(flash_kernel,
        cudaFuncAttributeMaxDynamicSharedMemorySize, FLASH_SMEM);

    prep_all<<<(N_TOT + 255)/256, 256>>>(hidden, Wq, Wk, Wv, dist_emb);
    qkv_mma<<<dim3(H_/64, M_/128, 3), 128, QKV_SMEM>>>(bq, bk, bv);
    flash_kernel<<<dim3(L_/64, BH_), 128, FLASH_SMEM>>>(mask, out);
}